// round 12
// baseline (speedup 1.0000x reference)
#include <cuda_runtime.h>
#include <cuda_fp16.h>

#define N_POIS 100000
#define N_HE   50000
#define NNZ    1600000
#define D      256
#define NB     128          // scan blocks per matrix

// ---------------- scratch (allocation-free device globals) ----------------
__device__ __half g_pois_h[(size_t)N_POIS * D];   // 51.2 MB fp16 gather copy
__device__ __half g_msg_tar_h[(size_t)N_HE * D];  // 25.6 MB fp16 intermediate
__device__ __half g_embs_h[(size_t)N_POIS * D];   // 51.2 MB fp16 e1
__device__ float  g_w[3];

__device__ int  g_cnt_tar[N_HE + 1];    // zero at entry; re-zeroed by scanAC
__device__ int  g_cnt_src[N_POIS + 1];
__device__ int  g_ptr_tar[N_HE + 1];
__device__ int  g_cur_tar[N_HE];
__device__ int2 g_pairs_tar[NNZ];
__device__ int  g_ptr_src[N_POIS + 1];
__device__ int  g_cur_src[N_POIS];
__device__ int2 g_pairs_src[NNZ];
__device__ int  g_bsums[2 * NB];
__device__ unsigned long long g_bar[2];  // monotonic ticket barriers (tar, src)

// ---------------------------------------------------------------------------
__device__ __forceinline__ unsigned pack2(float x, float y) {
    __half2 h = __floats2half2_rn(x, y);
    return *reinterpret_cast<unsigned*>(&h);
}
__device__ __forceinline__ float2 unpack2(unsigned u) {
    __half2 h = *reinterpret_cast<__half2*>(&u);
    return __half22float2(h);
}

// ---------------------------------------------------------------------------
// 8 edges per thread, two int4 loads (NNZ % 8 == 0). cnt must be zero at entry.
__global__ void __launch_bounds__(256) hist_one_kernel(const int4* __restrict__ r,
                                                       int* __restrict__ c) {
    int e = blockIdx.x * 256 + threadIdx.x;
    if (e >= NNZ / 8) return;
    int4 a = __ldcs(r + 2 * e);
    int4 b = __ldcs(r + 2 * e + 1);
    atomicAdd(&c[a.x + 1], 1); atomicAdd(&c[a.y + 1], 1);
    atomicAdd(&c[a.z + 1], 1); atomicAdd(&c[a.w + 1], 1);
    atomicAdd(&c[b.x + 1], 1); atomicAdd(&c[b.y + 1], 1);
    atomicAdd(&c[b.z + 1], 1); atomicAdd(&c[b.w + 1], 1);
}

// Fused two-phase scan: block partial sums -> grid barrier -> full prefix.
// Reads cnt, writes ptr + cur, and RE-ZEROS cnt (restores the invariant).
// Grid barrier = monotonic ticket counter (replay-safe, no reset).
__global__ void __launch_bounds__(256) scanAC_kernel(int* __restrict__ cnt, int len,
                                                     int* __restrict__ bsums,
                                                     int* __restrict__ ptr,
                                                     int* __restrict__ cur,
                                                     unsigned long long* __restrict__ bar) {
    __shared__ int s[256];
    __shared__ int bs[NB];
    int t = threadIdx.x, blk = blockIdx.x;
    int chunk = (len + NB - 1) / NB;
    int lo = blk * chunk, hi = min(len, lo + chunk);
    int sub = (chunk + 255) >> 8;
    int a = lo + t * sub, b = min(hi, a + sub);

    int sum = 0;
    for (int i = a; i < b; i++) sum += cnt[i];
    s[t] = sum;
    __syncthreads();
    int acc = s[t];
    for (int d = 1; d < 256; d <<= 1) {
        int v = (t >= d) ? s[t - d] : 0;
        __syncthreads();
        s[t] = acc = acc + v;
        __syncthreads();
        acc = s[t];
    }
    if (t == 0) {
        bsums[blk] = s[255];            // block total
        __threadfence();
        unsigned long long ticket = atomicAdd(bar, 1ULL);
        unsigned long long target = (ticket / NB + 1ULL) * NB;
        while (*(volatile unsigned long long*)bar < target) {}
    }
    __syncthreads();

    if (t < NB) bs[t] = __ldcg(bsums + t);
    __syncthreads();
    for (int d = 1; d < NB; d <<= 1) {
        int v = (t >= d && t < NB) ? bs[t - d] : 0;
        __syncthreads();
        if (t < NB) bs[t] += v;
        __syncthreads();
    }
    int base = (blk == 0) ? 0 : bs[blk - 1];

    int off = base + ((t == 0) ? 0 : s[t - 1]);
    for (int i = a; i < b; i++) {
        off += cnt[i];
        ptr[i] = off;
        if (i < len - 1) cur[i] = off;  // cur[row] = ptr[row]
        cnt[i] = 0;                     // restore zero invariant
    }
}

// 8 edges per thread; ALL 8 atomics issued before ANY store (MLP=8 on ATOMG)
__global__ void __launch_bounds__(256) scatter_one_kernel(
    const int4* __restrict__ r4, const int4* __restrict__ c4,
    const float4* __restrict__ v4, int* __restrict__ cur, int2* __restrict__ pairs)
{
    int e = blockIdx.x * 256 + threadIdx.x;
    if (e >= NNZ / 8) return;
    int4   r0 = __ldcs(r4 + 2 * e),     r1 = __ldcs(r4 + 2 * e + 1);
    int4   c0 = __ldcs(c4 + 2 * e),     c1 = __ldcs(c4 + 2 * e + 1);
    float4 v0 = __ldcs(v4 + 2 * e),     v1 = __ldcs(v4 + 2 * e + 1);
    int p0 = atomicAdd(&cur[r0.x], 1);
    int p1 = atomicAdd(&cur[r0.y], 1);
    int p2 = atomicAdd(&cur[r0.z], 1);
    int p3 = atomicAdd(&cur[r0.w], 1);
    int p4 = atomicAdd(&cur[r1.x], 1);
    int p5 = atomicAdd(&cur[r1.y], 1);
    int p6 = atomicAdd(&cur[r1.z], 1);
    int p7 = atomicAdd(&cur[r1.w], 1);
    pairs[p0] = make_int2(c0.x, __float_as_int(v0.x));
    pairs[p1] = make_int2(c0.y, __float_as_int(v0.y));
    pairs[p2] = make_int2(c0.z, __float_as_int(v0.z));
    pairs[p3] = make_int2(c0.w, __float_as_int(v0.w));
    pairs[p4] = make_int2(c1.x, __float_as_int(v1.x));
    pairs[p5] = make_int2(c1.y, __float_as_int(v1.y));
    pairs[p6] = make_int2(c1.z, __float_as_int(v1.z));
    pairs[p7] = make_int2(c1.w, __float_as_int(v1.w));
}

// fp32 -> fp16 copy (8 elems/thread), LINEAR layout; thread 0 also does softmax
__global__ void __launch_bounds__(256) tohalf_kernel(const float4* __restrict__ in,
                                                     uint4* __restrict__ out, int n8,
                                                     const float* __restrict__ attn) {
    int i = blockIdx.x * 256 + threadIdx.x;
    if (i == 0) {
        float a0 = attn[0], a1 = attn[1], a2 = attn[2];
        float m = fmaxf(a0, fmaxf(a1, a2));
        float e0 = expf(a0 - m), e1 = expf(a1 - m), e2 = expf(a2 - m);
        float inv = 1.0f / (e0 + e1 + e2);
        g_w[0] = e0 * inv; g_w[1] = e1 * inv; g_w[2] = e2 * inv;
    }
    if (i >= n8) return;
    float4 a = __ldcs(in + 2 * i), b = __ldcs(in + 2 * i + 1);
    uint4 o;
    o.x = pack2(a.x, a.y); o.y = pack2(a.z, a.w);
    o.z = pack2(b.x, b.y); o.w = pack2(b.z, b.w);
    out[i] = o;
}

// ---------------------------------------------------------------------------
// fp16 gather: warp per row; lane owns CONTIGUOUS elements [lane*8, lane*8+8).
// Pairs are read as uniform broadcast loads (all lanes same address, L1-hit).
__device__ __forceinline__ void gather_row_h(const int* __restrict__ ptr,
                                             const int2* __restrict__ pairs,
                                             const __half* __restrict__ dense,
                                             int row, int lane,
                                             float4& a0, float4& a1) {
    int start = __ldg(ptr + row), end = __ldg(ptr + row + 1);
    #pragma unroll 4
    for (int j = start; j < end; j++) {
        int2 pr = __ldg(pairs + j);                 // uniform across warp
        float v = __int_as_float(pr.y);
        uint4 u = __ldg(reinterpret_cast<const uint4*>(dense + (size_t)pr.x * D) + lane);
        float2 f0 = unpack2(u.x), f1 = unpack2(u.y);
        float2 f2 = unpack2(u.z), f3 = unpack2(u.w);
        a0.x = fmaf(v, f0.x, a0.x); a0.y = fmaf(v, f0.y, a0.y);
        a0.z = fmaf(v, f1.x, a0.z); a0.w = fmaf(v, f1.y, a0.w);
        a1.x = fmaf(v, f2.x, a1.x); a1.y = fmaf(v, f2.y, a1.y);
        a1.z = fmaf(v, f3.x, a1.z); a1.w = fmaf(v, f3.y, a1.w);
    }
}

__global__ void __launch_bounds__(256) spmm_tar_kernel(const int*  __restrict__ ptr,
                                                       const int2* __restrict__ pairs,
                                                       const __half* __restrict__ dense,
                                                       __half* __restrict__ out) {
    int row = (blockIdx.x * 256 + threadIdx.x) >> 5;
    if (row >= N_HE) return;
    int lane = threadIdx.x & 31;
    float4 a0 = make_float4(0.f, 0.f, 0.f, 0.f), a1 = a0;
    gather_row_h(ptr, pairs, dense, row, lane, a0, a1);
    uint4 o;
    o.x = pack2(a0.x, a0.y); o.y = pack2(a0.z, a0.w);
    o.z = pack2(a1.x, a1.y); o.w = pack2(a1.z, a1.w);
    *(reinterpret_cast<uint4*>(out + (size_t)row * D) + lane) = o;   // linear
}

// Fused src-SpMM + epilogue.  a0/a1 are elements [lane*8, lane*8+8).
// LAYER 0: e1 = (relu(msg)*d1 + pois)*d2 ; embs_h = fp16(e1)
// LAYER 1: e2 = (relu(msg)*d1 + e1)*d2 ; out = w0*pois + w1*e1 + w2*e2
template<int LAYER>
__global__ void __launch_bounds__(256) spmm_src_fused_kernel(
    const int*  __restrict__ ptr,
    const int2* __restrict__ pairs,
    const __half* __restrict__ dense,   // msg_tar_h
    const float4* __restrict__ d1,
    const float4* __restrict__ d2,
    const uint4*  __restrict__ prev_h,  // L0: pois_h ; L1: embs_h
    const uint4*  __restrict__ pois_h,  // L1 only
    float4* __restrict__ outp,          // L1: out
    uint4*  __restrict__ out_h)         // L0: embs_h
{
    int row = (blockIdx.x * 256 + threadIdx.x) >> 5;
    if (row >= N_POIS) return;
    int lane = threadIdx.x & 31;
    float4 a0 = make_float4(0.f, 0.f, 0.f, 0.f), a1 = a0;
    gather_row_h(ptr, pairs, dense, row, lane, a0, a1);

    size_t i0 = (size_t)row * (D / 4) + 2 * lane;   // float4 pair for [lane*8, +8)
    size_t ih = (size_t)row * (D / 8) + lane;
    float4 m0 = __ldcs(d1 + i0),  m1 = __ldcs(d1 + i0 + 1);
    float4 q0 = __ldcs(d2 + i0),  q1 = __ldcs(d2 + i0 + 1);

    float4 p0, p1;
    {
        uint4 u = __ldg(prev_h + ih);
        float2 f0 = unpack2(u.x), f1 = unpack2(u.y);
        float2 f2 = unpack2(u.z), f3 = unpack2(u.w);
        p0 = make_float4(f0.x, f0.y, f1.x, f1.y);
        p1 = make_float4(f2.x, f2.y, f3.x, f3.y);
    }

    float4 e0, e1;
    e0.x = (fmaxf(a0.x, 0.f) * m0.x + p0.x) * q0.x;
    e0.y = (fmaxf(a0.y, 0.f) * m0.y + p0.y) * q0.y;
    e0.z = (fmaxf(a0.z, 0.f) * m0.z + p0.z) * q0.z;
    e0.w = (fmaxf(a0.w, 0.f) * m0.w + p0.w) * q0.w;
    e1.x = (fmaxf(a1.x, 0.f) * m1.x + p1.x) * q1.x;
    e1.y = (fmaxf(a1.y, 0.f) * m1.y + p1.y) * q1.y;
    e1.z = (fmaxf(a1.z, 0.f) * m1.z + p1.z) * q1.z;
    e1.w = (fmaxf(a1.w, 0.f) * m1.w + p1.w) * q1.w;

    if (LAYER == 0) {
        uint4 h;
        h.x = pack2(e0.x, e0.y); h.y = pack2(e0.z, e0.w);
        h.z = pack2(e1.x, e1.y); h.w = pack2(e1.z, e1.w);
        out_h[ih] = h;    // linear
    } else {
        float w0 = g_w[0], w1 = g_w[1], w2 = g_w[2];
        float4 z0, z1;
        {
            uint4 u = __ldg(pois_h + ih);
            float2 f0 = unpack2(u.x), f1 = unpack2(u.y);
            float2 f2 = unpack2(u.z), f3 = unpack2(u.w);
            z0 = make_float4(f0.x, f0.y, f1.x, f1.y);
            z1 = make_float4(f2.x, f2.y, f3.x, f3.y);
        }
        float4 o0, o1;
        o0.x = w0 * z0.x + w1 * p0.x + w2 * e0.x;
        o0.y = w0 * z0.y + w1 * p0.y + w2 * e0.y;
        o0.z = w0 * z0.z + w1 * p0.z + w2 * e0.z;
        o0.w = w0 * z0.w + w1 * p0.w + w2 * e0.w;
        o1.x = w0 * z1.x + w1 * p1.x + w2 * e1.x;
        o1.y = w0 * z1.y + w1 * p1.y + w2 * e1.y;
        o1.z = w0 * z1.z + w1 * p1.z + w2 * e1.z;
        o1.w = w0 * z1.w + w1 * p1.w + w2 * e1.w;
        __stcs(outp + i0,     o0);     // out never re-read: evict-first
        __stcs(outp + i0 + 1, o1);
    }
}

// ---------------------------------------------------------------------------
extern "C" void kernel_launch(void* const* d_in, const int* in_sizes, int n_in,
                              void* d_out, int out_size)
{
    const float* pois      = (const float*)d_in[0];
    const float* tar_vals  = (const float*)d_in[1];
    const float* src_vals  = (const float*)d_in[2];
    const float* attn      = (const float*)d_in[3];
    const float* drop1     = (const float*)d_in[4];
    const float* drop2     = (const float*)d_in[5];
    const int*   tar_rows  = (const int*)d_in[6];
    const int*   tar_cols  = (const int*)d_in[7];
    const int*   src_rows  = (const int*)d_in[8];
    const int*   src_cols  = (const int*)d_in[9];
    float*       out       = (float*)d_out;

    __half *pois_h, *msg_tar_h, *embs_h;
    int *cnt_tar, *cnt_src, *ptr_tar, *cur_tar, *ptr_src, *cur_src, *bsums;
    int2 *pairs_tar, *pairs_src;
    unsigned long long* bar;
    cudaGetSymbolAddress((void**)&pois_h,    g_pois_h);
    cudaGetSymbolAddress((void**)&msg_tar_h, g_msg_tar_h);
    cudaGetSymbolAddress((void**)&embs_h,    g_embs_h);
    cudaGetSymbolAddress((void**)&cnt_tar,   g_cnt_tar);
    cudaGetSymbolAddress((void**)&cnt_src,   g_cnt_src);
    cudaGetSymbolAddress((void**)&ptr_tar,   g_ptr_tar);
    cudaGetSymbolAddress((void**)&cur_tar,   g_cur_tar);
    cudaGetSymbolAddress((void**)&pairs_tar, g_pairs_tar);
    cudaGetSymbolAddress((void**)&ptr_src,   g_ptr_src);
    cudaGetSymbolAddress((void**)&cur_src,   g_cur_src);
    cudaGetSymbolAddress((void**)&pairs_src, g_pairs_src);
    cudaGetSymbolAddress((void**)&bsums,     g_bsums);
    cudaGetSymbolAddress((void**)&bar,       g_bar);

    // side stream + events, created once on the first (uncaptured) call
    static cudaStream_t s2 = nullptr;
    static cudaEvent_t evF = nullptr, evH = nullptr, evS = nullptr;
    if (s2 == nullptr) {
        cudaStreamCreateWithFlags(&s2, cudaStreamNonBlocking);
        cudaEventCreateWithFlags(&evF, cudaEventDisableTiming);
        cudaEventCreateWithFlags(&evH, cudaEventDisableTiming);
        cudaEventCreateWithFlags(&evS, cudaEventDisableTiming);
    }

    const int nnz8_blocks = (NNZ / 8 + 255) / 256;
    const size_t ld = (size_t)N_POIS * D;
    const int tar_blocks = (N_HE * 32 + 255) / 256;
    const int src_blocks = (N_POIS * 32 + 255) / 256;

    // ---- fork ----
    cudaEventRecord(evF, 0);
    cudaStreamWaitEvent(s2, evF, 0);

    // ---- s2: tohalf(+softmax), then src CSR build (hidden behind tar path) ----
    tohalf_kernel<<<(N_POIS * D / 8 + 255) / 256, 256, 0, s2>>>(
        (const float4*)pois, (uint4*)pois_h, N_POIS * D / 8, attn);
    cudaEventRecord(evH, s2);
    hist_one_kernel<<<nnz8_blocks, 256, 0, s2>>>((const int4*)src_rows, cnt_src);
    scanAC_kernel<<<NB, 256, 0, s2>>>(cnt_src, N_POIS + 1, bsums + NB,
                                      ptr_src, cur_src, bar + 1);
    scatter_one_kernel<<<nnz8_blocks, 256, 0, s2>>>(
        (const int4*)src_rows, (const int4*)src_cols, (const float4*)src_vals,
        cur_src, pairs_src);
    cudaEventRecord(evS, s2);

    // ---- s0: tar CSR build ----
    hist_one_kernel<<<nnz8_blocks, 256>>>((const int4*)tar_rows, cnt_tar);
    scanAC_kernel<<<NB, 256>>>(cnt_tar, N_HE + 1, bsums, ptr_tar, cur_tar, bar);
    scatter_one_kernel<<<nnz8_blocks, 256>>>(
        (const int4*)tar_rows, (const int4*)tar_cols, (const float4*)tar_vals,
        cur_tar, pairs_tar);

    // ---- layer 0 ----
    cudaStreamWaitEvent(0, evH, 0);          // need pois_h
    spmm_tar_kernel<<<tar_blocks, 256>>>(ptr_tar, pairs_tar, pois_h, msg_tar_h);
    cudaStreamWaitEvent(0, evS, 0);          // need src CSR (join s2)
    spmm_src_fused_kernel<0><<<src_blocks, 256>>>(ptr_src, pairs_src, msg_tar_h,
        (const float4*)drop1, (const float4*)drop2,
        (const uint4*)pois_h, nullptr, nullptr, (uint4*)embs_h);

    // ---- layer 1 ----
    spmm_tar_kernel<<<tar_blocks, 256>>>(ptr_tar, pairs_tar, embs_h, msg_tar_h);
    spmm_src_fused_kernel<1><<<src_blocks, 256>>>(ptr_src, pairs_src, msg_tar_h,
        (const float4*)(drop1 + ld), (const float4*)(drop2 + ld),
        (const uint4*)embs_h, (const uint4*)pois_h,
        (float4*)out, nullptr);
}

// round 13
// speedup vs baseline: 1.0033x; 1.0033x over previous
#include <cuda_runtime.h>
#include <cuda_fp16.h>

#define N_POIS 100000
#define N_HE   50000
#define NNZ    1600000
#define D      256
#define NB     128          // scan blocks per matrix

// ---------------- scratch (allocation-free device globals) ----------------
__device__ __half g_pois_h[(size_t)N_POIS * D];   // 51.2 MB fp16 gather copy
__device__ __half g_msg_tar_h[(size_t)N_HE * D];  // 25.6 MB fp16 intermediate
__device__ __half g_embs_h[(size_t)N_POIS * D];   // 51.2 MB fp16 e1
__device__ float  g_w[3];

__device__ int  g_cnt_tar[N_HE + 1];    // zero at entry; re-zeroed by scanAC
__device__ int  g_cnt_src[N_POIS + 1];
__device__ int  g_ptr_tar[N_HE + 1];
__device__ int  g_cur_tar[N_HE];
__device__ int2 g_pairs_tar[NNZ];
__device__ int  g_ptr_src[N_POIS + 1];
__device__ int  g_cur_src[N_POIS];
__device__ int2 g_pairs_src[NNZ];
__device__ int  g_bsums[2 * NB];
__device__ unsigned long long g_bar[2];  // monotonic ticket barriers (tar, src)

// ---------------------------------------------------------------------------
__device__ __forceinline__ unsigned pack2(float x, float y) {
    __half2 h = __floats2half2_rn(x, y);
    return *reinterpret_cast<unsigned*>(&h);
}
__device__ __forceinline__ float2 unpack2(unsigned u) {
    __half2 h = *reinterpret_cast<__half2*>(&u);
    return __half22float2(h);
}

// ---------------------------------------------------------------------------
// 8 edges per thread, two int4 loads (NNZ % 8 == 0). cnt must be zero at entry.
__global__ void __launch_bounds__(256) hist_one_kernel(const int4* __restrict__ r,
                                                       int* __restrict__ c) {
    int e = blockIdx.x * 256 + threadIdx.x;
    if (e >= NNZ / 8) return;
    int4 a = __ldcs(r + 2 * e);
    int4 b = __ldcs(r + 2 * e + 1);
    atomicAdd(&c[a.x + 1], 1); atomicAdd(&c[a.y + 1], 1);
    atomicAdd(&c[a.z + 1], 1); atomicAdd(&c[a.w + 1], 1);
    atomicAdd(&c[b.x + 1], 1); atomicAdd(&c[b.y + 1], 1);
    atomicAdd(&c[b.z + 1], 1); atomicAdd(&c[b.w + 1], 1);
}

// Fused two-phase scan: block partial sums -> grid barrier -> full prefix.
// Reads cnt, writes ptr + cur, and RE-ZEROS cnt (restores the invariant).
// Grid barrier = monotonic ticket counter (replay-safe, no reset).
__global__ void __launch_bounds__(256) scanAC_kernel(int* __restrict__ cnt, int len,
                                                     int* __restrict__ bsums,
                                                     int* __restrict__ ptr,
                                                     int* __restrict__ cur,
                                                     unsigned long long* __restrict__ bar) {
    __shared__ int s[256];
    __shared__ int bs[NB];
    int t = threadIdx.x, blk = blockIdx.x;
    int chunk = (len + NB - 1) / NB;
    int lo = blk * chunk, hi = min(len, lo + chunk);
    int sub = (chunk + 255) >> 8;
    int a = lo + t * sub, b = min(hi, a + sub);

    int sum = 0;
    for (int i = a; i < b; i++) sum += cnt[i];
    s[t] = sum;
    __syncthreads();
    int acc = s[t];
    for (int d = 1; d < 256; d <<= 1) {
        int v = (t >= d) ? s[t - d] : 0;
        __syncthreads();
        s[t] = acc = acc + v;
        __syncthreads();
        acc = s[t];
    }
    if (t == 0) {
        bsums[blk] = s[255];            // block total
        __threadfence();
        unsigned long long ticket = atomicAdd(bar, 1ULL);
        unsigned long long target = (ticket / NB + 1ULL) * NB;
        while (*(volatile unsigned long long*)bar < target) {}
    }
    __syncthreads();

    if (t < NB) bs[t] = __ldcg(bsums + t);
    __syncthreads();
    for (int d = 1; d < NB; d <<= 1) {
        int v = (t >= d && t < NB) ? bs[t - d] : 0;
        __syncthreads();
        if (t < NB) bs[t] += v;
        __syncthreads();
    }
    int base = (blk == 0) ? 0 : bs[blk - 1];

    int off = base + ((t == 0) ? 0 : s[t - 1]);
    for (int i = a; i < b; i++) {
        off += cnt[i];
        ptr[i] = off;
        if (i < len - 1) cur[i] = off;  // cur[row] = ptr[row]
        cnt[i] = 0;                     // restore zero invariant
    }
}

// 8 edges per thread, two int4/float4 loads each (R10 form: regs 32, occ ~69%)
__global__ void __launch_bounds__(256) scatter_one_kernel(
    const int4* __restrict__ r4, const int4* __restrict__ c4,
    const float4* __restrict__ v4, int* __restrict__ cur, int2* __restrict__ pairs)
{
    int e = blockIdx.x * 256 + threadIdx.x;
    if (e >= NNZ / 8) return;
    int4   r0 = __ldcs(r4 + 2 * e),     r1 = __ldcs(r4 + 2 * e + 1);
    int4   c0 = __ldcs(c4 + 2 * e),     c1 = __ldcs(c4 + 2 * e + 1);
    float4 v0 = __ldcs(v4 + 2 * e),     v1 = __ldcs(v4 + 2 * e + 1);
    pairs[atomicAdd(&cur[r0.x], 1)] = make_int2(c0.x, __float_as_int(v0.x));
    pairs[atomicAdd(&cur[r0.y], 1)] = make_int2(c0.y, __float_as_int(v0.y));
    pairs[atomicAdd(&cur[r0.z], 1)] = make_int2(c0.z, __float_as_int(v0.z));
    pairs[atomicAdd(&cur[r0.w], 1)] = make_int2(c0.w, __float_as_int(v0.w));
    pairs[atomicAdd(&cur[r1.x], 1)] = make_int2(c1.x, __float_as_int(v1.x));
    pairs[atomicAdd(&cur[r1.y], 1)] = make_int2(c1.y, __float_as_int(v1.y));
    pairs[atomicAdd(&cur[r1.z], 1)] = make_int2(c1.z, __float_as_int(v1.z));
    pairs[atomicAdd(&cur[r1.w], 1)] = make_int2(c1.w, __float_as_int(v1.w));
}

// fp32 -> fp16 copy (8 elems/thread), LINEAR layout; thread 0 also does softmax
__global__ void __launch_bounds__(256) tohalf_kernel(const float4* __restrict__ in,
                                                     uint4* __restrict__ out, int n8,
                                                     const float* __restrict__ attn) {
    int i = blockIdx.x * 256 + threadIdx.x;
    if (i == 0) {
        float a0 = attn[0], a1 = attn[1], a2 = attn[2];
        float m = fmaxf(a0, fmaxf(a1, a2));
        float e0 = expf(a0 - m), e1 = expf(a1 - m), e2 = expf(a2 - m);
        float inv = 1.0f / (e0 + e1 + e2);
        g_w[0] = e0 * inv; g_w[1] = e1 * inv; g_w[2] = e2 * inv;
    }
    if (i >= n8) return;
    float4 a = __ldcs(in + 2 * i), b = __ldcs(in + 2 * i + 1);
    uint4 o;
    o.x = pack2(a.x, a.y); o.y = pack2(a.z, a.w);
    o.z = pack2(b.x, b.y); o.w = pack2(b.z, b.w);
    out[i] = o;
}

// ---------------------------------------------------------------------------
// fp16 gather: warp per row; lane owns CONTIGUOUS elements [lane*8, lane*8+8).
// Pairs are read as uniform broadcast loads (all lanes same address, L1-hit).
__device__ __forceinline__ void gather_row_h(const int* __restrict__ ptr,
                                             const int2* __restrict__ pairs,
                                             const __half* __restrict__ dense,
                                             int row, int lane,
                                             float4& a0, float4& a1) {
    int start = __ldg(ptr + row), end = __ldg(ptr + row + 1);
    #pragma unroll 4
    for (int j = start; j < end; j++) {
        int2 pr = __ldg(pairs + j);                 // uniform across warp
        float v = __int_as_float(pr.y);
        uint4 u = __ldg(reinterpret_cast<const uint4*>(dense + (size_t)pr.x * D) + lane);
        float2 f0 = unpack2(u.x), f1 = unpack2(u.y);
        float2 f2 = unpack2(u.z), f3 = unpack2(u.w);
        a0.x = fmaf(v, f0.x, a0.x); a0.y = fmaf(v, f0.y, a0.y);
        a0.z = fmaf(v, f1.x, a0.z); a0.w = fmaf(v, f1.y, a0.w);
        a1.x = fmaf(v, f2.x, a1.x); a1.y = fmaf(v, f2.y, a1.y);
        a1.z = fmaf(v, f3.x, a1.z); a1.w = fmaf(v, f3.y, a1.w);
    }
}

__global__ void __launch_bounds__(256) spmm_tar_kernel(const int*  __restrict__ ptr,
                                                       const int2* __restrict__ pairs,
                                                       const __half* __restrict__ dense,
                                                       __half* __restrict__ out) {
    int row = (blockIdx.x * 256 + threadIdx.x) >> 5;
    if (row >= N_HE) return;
    int lane = threadIdx.x & 31;
    float4 a0 = make_float4(0.f, 0.f, 0.f, 0.f), a1 = a0;
    gather_row_h(ptr, pairs, dense, row, lane, a0, a1);
    uint4 o;
    o.x = pack2(a0.x, a0.y); o.y = pack2(a0.z, a0.w);
    o.z = pack2(a1.x, a1.y); o.w = pack2(a1.z, a1.w);
    *(reinterpret_cast<uint4*>(out + (size_t)row * D) + lane) = o;   // linear
}

// Fused src-SpMM + epilogue.  a0/a1 are elements [lane*8, lane*8+8).
// LAYER 0: e1 = (relu(msg)*d1 + pois)*d2 ; embs_h = fp16(e1)
// LAYER 1: e2 = (relu(msg)*d1 + e1)*d2 ; out = w0*pois + w1*e1 + w2*e2
template<int LAYER>
__global__ void __launch_bounds__(256) spmm_src_fused_kernel(
    const int*  __restrict__ ptr,
    const int2* __restrict__ pairs,
    const __half* __restrict__ dense,   // msg_tar_h
    const float4* __restrict__ d1,
    const float4* __restrict__ d2,
    const uint4*  __restrict__ prev_h,  // L0: pois_h ; L1: embs_h
    const uint4*  __restrict__ pois_h,  // L1 only
    float4* __restrict__ outp,          // L1: out
    uint4*  __restrict__ out_h)         // L0: embs_h
{
    int row = (blockIdx.x * 256 + threadIdx.x) >> 5;
    if (row >= N_POIS) return;
    int lane = threadIdx.x & 31;
    float4 a0 = make_float4(0.f, 0.f, 0.f, 0.f), a1 = a0;
    gather_row_h(ptr, pairs, dense, row, lane, a0, a1);

    size_t i0 = (size_t)row * (D / 4) + 2 * lane;   // float4 pair for [lane*8, +8)
    size_t ih = (size_t)row * (D / 8) + lane;
    float4 m0 = __ldcs(d1 + i0),  m1 = __ldcs(d1 + i0 + 1);
    float4 q0 = __ldcs(d2 + i0),  q1 = __ldcs(d2 + i0 + 1);

    float4 p0, p1;
    {
        uint4 u = __ldg(prev_h + ih);
        float2 f0 = unpack2(u.x), f1 = unpack2(u.y);
        float2 f2 = unpack2(u.z), f3 = unpack2(u.w);
        p0 = make_float4(f0.x, f0.y, f1.x, f1.y);
        p1 = make_float4(f2.x, f2.y, f3.x, f3.y);
    }

    float4 e0, e1;
    e0.x = (fmaxf(a0.x, 0.f) * m0.x + p0.x) * q0.x;
    e0.y = (fmaxf(a0.y, 0.f) * m0.y + p0.y) * q0.y;
    e0.z = (fmaxf(a0.z, 0.f) * m0.z + p0.z) * q0.z;
    e0.w = (fmaxf(a0.w, 0.f) * m0.w + p0.w) * q0.w;
    e1.x = (fmaxf(a1.x, 0.f) * m1.x + p1.x) * q1.x;
    e1.y = (fmaxf(a1.y, 0.f) * m1.y + p1.y) * q1.y;
    e1.z = (fmaxf(a1.z, 0.f) * m1.z + p1.z) * q1.z;
    e1.w = (fmaxf(a1.w, 0.f) * m1.w + p1.w) * q1.w;

    if (LAYER == 0) {
        uint4 h;
        h.x = pack2(e0.x, e0.y); h.y = pack2(e0.z, e0.w);
        h.z = pack2(e1.x, e1.y); h.w = pack2(e1.z, e1.w);
        out_h[ih] = h;    // linear
    } else {
        float w0 = g_w[0], w1 = g_w[1], w2 = g_w[2];
        float4 z0, z1;
        {
            uint4 u = __ldg(pois_h + ih);
            float2 f0 = unpack2(u.x), f1 = unpack2(u.y);
            float2 f2 = unpack2(u.z), f3 = unpack2(u.w);
            z0 = make_float4(f0.x, f0.y, f1.x, f1.y);
            z1 = make_float4(f2.x, f2.y, f3.x, f3.y);
        }
        float4 o0, o1;
        o0.x = w0 * z0.x + w1 * p0.x + w2 * e0.x;
        o0.y = w0 * z0.y + w1 * p0.y + w2 * e0.y;
        o0.z = w0 * z0.z + w1 * p0.z + w2 * e0.z;
        o0.w = w0 * z0.w + w1 * p0.w + w2 * e0.w;
        o1.x = w0 * z1.x + w1 * p1.x + w2 * e1.x;
        o1.y = w0 * z1.y + w1 * p1.y + w2 * e1.y;
        o1.z = w0 * z1.z + w1 * p1.z + w2 * e1.z;
        o1.w = w0 * z1.w + w1 * p1.w + w2 * e1.w;
        outp[i0]     = o0;     // plain stores (R12's __stcs regressed badly)
        outp[i0 + 1] = o1;
    }
}

// ---------------------------------------------------------------------------
extern "C" void kernel_launch(void* const* d_in, const int* in_sizes, int n_in,
                              void* d_out, int out_size)
{
    const float* pois      = (const float*)d_in[0];
    const float* tar_vals  = (const float*)d_in[1];
    const float* src_vals  = (const float*)d_in[2];
    const float* attn      = (const float*)d_in[3];
    const float* drop1     = (const float*)d_in[4];
    const float* drop2     = (const float*)d_in[5];
    const int*   tar_rows  = (const int*)d_in[6];
    const int*   tar_cols  = (const int*)d_in[7];
    const int*   src_rows  = (const int*)d_in[8];
    const int*   src_cols  = (const int*)d_in[9];
    float*       out       = (float*)d_out;

    __half *pois_h, *msg_tar_h, *embs_h;
    int *cnt_tar, *cnt_src, *ptr_tar, *cur_tar, *ptr_src, *cur_src, *bsums;
    int2 *pairs_tar, *pairs_src;
    unsigned long long* bar;
    cudaGetSymbolAddress((void**)&pois_h,    g_pois_h);
    cudaGetSymbolAddress((void**)&msg_tar_h, g_msg_tar_h);
    cudaGetSymbolAddress((void**)&embs_h,    g_embs_h);
    cudaGetSymbolAddress((void**)&cnt_tar,   g_cnt_tar);
    cudaGetSymbolAddress((void**)&cnt_src,   g_cnt_src);
    cudaGetSymbolAddress((void**)&ptr_tar,   g_ptr_tar);
    cudaGetSymbolAddress((void**)&cur_tar,   g_cur_tar);
    cudaGetSymbolAddress((void**)&pairs_tar, g_pairs_tar);
    cudaGetSymbolAddress((void**)&ptr_src,   g_ptr_src);
    cudaGetSymbolAddress((void**)&cur_src,   g_cur_src);
    cudaGetSymbolAddress((void**)&pairs_src, g_pairs_src);
    cudaGetSymbolAddress((void**)&bsums,     g_bsums);
    cudaGetSymbolAddress((void**)&bar,       g_bar);

    // side stream + events, created once on the first (uncaptured) call
    static cudaStream_t s2 = nullptr;
    static cudaEvent_t evF = nullptr, evH = nullptr, evS = nullptr;
    if (s2 == nullptr) {
        cudaStreamCreateWithFlags(&s2, cudaStreamNonBlocking);
        cudaEventCreateWithFlags(&evF, cudaEventDisableTiming);
        cudaEventCreateWithFlags(&evH, cudaEventDisableTiming);
        cudaEventCreateWithFlags(&evS, cudaEventDisableTiming);
    }

    const int nnz8_blocks = (NNZ / 8 + 255) / 256;
    const size_t ld = (size_t)N_POIS * D;
    const int tar_blocks = (N_HE * 32 + 255) / 256;
    const int src_blocks = (N_POIS * 32 + 255) / 256;

    // ---- fork ----
    cudaEventRecord(evF, 0);
    cudaStreamWaitEvent(s2, evF, 0);

    // ---- s2: tohalf(+softmax), then src CSR build (hidden behind tar path) ----
    tohalf_kernel<<<(N_POIS * D / 8 + 255) / 256, 256, 0, s2>>>(
        (const float4*)pois, (uint4*)pois_h, N_POIS * D / 8, attn);
    cudaEventRecord(evH, s2);
    hist_one_kernel<<<nnz8_blocks, 256, 0, s2>>>((const int4*)src_rows, cnt_src);
    scanAC_kernel<<<NB, 256, 0, s2>>>(cnt_src, N_POIS + 1, bsums + NB,
                                      ptr_src, cur_src, bar + 1);
    scatter_one_kernel<<<nnz8_blocks, 256, 0, s2>>>(
        (const int4*)src_rows, (const int4*)src_cols, (const float4*)src_vals,
        cur_src, pairs_src);
    cudaEventRecord(evS, s2);

    // ---- s0: tar CSR build ----
    hist_one_kernel<<<nnz8_blocks, 256>>>((const int4*)tar_rows, cnt_tar);
    scanAC_kernel<<<NB, 256>>>(cnt_tar, N_HE + 1, bsums, ptr_tar, cur_tar, bar);
    scatter_one_kernel<<<nnz8_blocks, 256>>>(
        (const int4*)tar_rows, (const int4*)tar_cols, (const float4*)tar_vals,
        cur_tar, pairs_tar);

    // ---- layer 0 ----
    cudaStreamWaitEvent(0, evH, 0);          // need pois_h
    spmm_tar_kernel<<<tar_blocks, 256>>>(ptr_tar, pairs_tar, pois_h, msg_tar_h);
    cudaStreamWaitEvent(0, evS, 0);          // need src CSR (join s2)
    spmm_src_fused_kernel<0><<<src_blocks, 256>>>(ptr_src, pairs_src, msg_tar_h,
        (const float4*)drop1, (const float4*)drop2,
        (const uint4*)pois_h, nullptr, nullptr, (uint4*)embs_h);

    // ---- layer 1 ----
    spmm_tar_kernel<<<tar_blocks, 256>>>(ptr_tar, pairs_tar, embs_h, msg_tar_h);
    spmm_src_fused_kernel<1><<<src_blocks, 256>>>(ptr_src, pairs_src, msg_tar_h,
        (const float4*)(drop1 + ld), (const float4*)(drop2 + ld),
        (const uint4*)embs_h, (const uint4*)pois_h,
        (float4*)out, nullptr);
}

// round 14
// speedup vs baseline: 1.3056x; 1.3013x over previous
#include <cuda_runtime.h>
#include <cuda_fp16.h>

#define N_POIS 100000
#define N_HE   50000
#define NNZ    1600000
#define D      256
#define NB     128          // scan blocks per matrix

// ---------------- scratch (allocation-free device globals) ----------------
__device__ __half g_pois_h[(size_t)N_POIS * D];   // 51.2 MB fp16 gather copy
__device__ __half g_msg_tar_h[(size_t)N_HE * D];  // 25.6 MB fp16 intermediate
__device__ __half g_embs_h[(size_t)N_POIS * D];   // 51.2 MB fp16 e1
__device__ float  g_w[3];

__device__ int  g_ptr_tar[N_HE + 1];
__device__ int  g_cur_tar[N_HE];
__device__ int2 g_pairs_tar[NNZ];
__device__ int  g_ptr_src[N_POIS + 1];
__device__ int  g_cur_src[N_POIS];
__device__ int2 g_pairs_src[NNZ];
__device__ int  g_bsums[2 * NB];

// ---------------------------------------------------------------------------
__device__ __forceinline__ unsigned pack2(float x, float y) {
    __half2 h = __floats2half2_rn(x, y);
    return *reinterpret_cast<unsigned*>(&h);
}
__device__ __forceinline__ float2 unpack2(unsigned u) {
    __half2 h = *reinterpret_cast<__half2*>(&u);
    return __half22float2(h);
}

// ---------------------------------------------------------------------------
// zero one ptr array; optionally block 0 thread 0 computes softmax weights
__global__ void __launch_bounds__(256) zero_one_kernel(int* __restrict__ p, int n,
                                                       const float* __restrict__ attn) {
    int i = blockIdx.x * 256 + threadIdx.x;
    if (i == 0 && attn) {
        float a0 = attn[0], a1 = attn[1], a2 = attn[2];
        float m = fmaxf(a0, fmaxf(a1, a2));
        float e0 = expf(a0 - m), e1 = expf(a1 - m), e2 = expf(a2 - m);
        float inv = 1.0f / (e0 + e1 + e2);
        g_w[0] = e0 * inv; g_w[1] = e1 * inv; g_w[2] = e2 * inv;
    }
    if (i < n) p[i] = 0;
}

// 8 edges per thread, two int4 loads (NNZ % 8 == 0)
__global__ void __launch_bounds__(256) hist_one_kernel(const int4* __restrict__ r,
                                                       int* __restrict__ c) {
    int e = blockIdx.x * 256 + threadIdx.x;
    if (e >= NNZ / 8) return;
    int4 a = __ldcs(r + 2 * e);
    int4 b = __ldcs(r + 2 * e + 1);
    atomicAdd(&c[a.x + 1], 1); atomicAdd(&c[a.y + 1], 1);
    atomicAdd(&c[a.z + 1], 1); atomicAdd(&c[a.w + 1], 1);
    atomicAdd(&c[b.x + 1], 1); atomicAdd(&c[b.y + 1], 1);
    atomicAdd(&c[b.z + 1], 1); atomicAdd(&c[b.w + 1], 1);
}

// ---- multi-block scan (single matrix): A (raw block sums) + C (fused) ----
__global__ void __launch_bounds__(256) scanA_kernel(const int* __restrict__ p, int len,
                                                    int* __restrict__ bsums) {
    __shared__ int red[256];
    int chunk = (len + NB - 1) / NB;
    int lo = blockIdx.x * chunk, hi = min(len, lo + chunk);
    int sub = (chunk + 255) >> 8;
    int a = lo + threadIdx.x * sub, b = min(hi, a + sub);
    int s = 0;
    for (int i = a; i < b; i++) s += p[i];
    red[threadIdx.x] = s;
    __syncthreads();
    for (int d = 128; d > 0; d >>= 1) {
        if (threadIdx.x < d) red[threadIdx.x] += red[threadIdx.x + d];
        __syncthreads();
    }
    if (threadIdx.x == 0) bsums[blockIdx.x] = red[0];
}

// scanC with in-kernel PARALLEL scan of the raw block sums (no extra launch)
__global__ void __launch_bounds__(256) scanC_kernel(int* __restrict__ p, int len,
                                                    const int* __restrict__ bsums,
                                                    int* __restrict__ cur) {
    __shared__ int s[256];
    __shared__ int bs[NB];
    int t = threadIdx.x;
    int blk = blockIdx.x;

    // inclusive scan of the NB raw block sums (log steps, parallel)
    if (t < NB) bs[t] = bsums[t];
    __syncthreads();
    for (int d = 1; d < NB; d <<= 1) {
        int v = (t >= d && t < NB) ? bs[t - d] : 0;
        __syncthreads();
        if (t < NB) bs[t] += v;
        __syncthreads();
    }
    int base = (blk == 0) ? 0 : bs[blk - 1];

    int chunk = (len + NB - 1) / NB;
    int lo = blk * chunk, hi = min(len, lo + chunk);
    int sub = (chunk + 255) >> 8;
    int a = lo + t * sub, b = min(hi, a + sub);
    int sum = 0;
    for (int i = a; i < b; i++) sum += p[i];
    s[t] = sum;
    __syncthreads();
    int acc = s[t];
    for (int d = 1; d < 256; d <<= 1) {
        int v = (t >= d) ? s[t - d] : 0;
        __syncthreads();
        s[t] = acc = acc + v;
        __syncthreads();
        acc = s[t];
    }
    int off = base + ((t == 0) ? 0 : s[t - 1]);
    for (int i = a; i < b; i++) {
        off += p[i];
        p[i] = off;
        if (i < len - 1) cur[i] = off;    // cur[row] = ptr[row]
    }
}

// 8 edges per thread, two int4/float4 loads each
__global__ void __launch_bounds__(256) scatter_one_kernel(
    const int4* __restrict__ r4, const int4* __restrict__ c4,
    const float4* __restrict__ v4, int* __restrict__ cur, int2* __restrict__ pairs)
{
    int e = blockIdx.x * 256 + threadIdx.x;
    if (e >= NNZ / 8) return;
    int4   r0 = __ldcs(r4 + 2 * e),     r1 = __ldcs(r4 + 2 * e + 1);
    int4   c0 = __ldcs(c4 + 2 * e),     c1 = __ldcs(c4 + 2 * e + 1);
    float4 v0 = __ldcs(v4 + 2 * e),     v1 = __ldcs(v4 + 2 * e + 1);
    pairs[atomicAdd(&cur[r0.x], 1)] = make_int2(c0.x, __float_as_int(v0.x));
    pairs[atomicAdd(&cur[r0.y], 1)] = make_int2(c0.y, __float_as_int(v0.y));
    pairs[atomicAdd(&cur[r0.z], 1)] = make_int2(c0.z, __float_as_int(v0.z));
    pairs[atomicAdd(&cur[r0.w], 1)] = make_int2(c0.w, __float_as_int(v0.w));
    pairs[atomicAdd(&cur[r1.x], 1)] = make_int2(c1.x, __float_as_int(v1.x));
    pairs[atomicAdd(&cur[r1.y], 1)] = make_int2(c1.y, __float_as_int(v1.y));
    pairs[atomicAdd(&cur[r1.z], 1)] = make_int2(c1.z, __float_as_int(v1.z));
    pairs[atomicAdd(&cur[r1.w], 1)] = make_int2(c1.w, __float_as_int(v1.w));
}

// fp32 -> fp16 copy (8 elems/thread), LINEAR layout
__global__ void __launch_bounds__(256) tohalf_kernel(const float4* __restrict__ in,
                                                     uint4* __restrict__ out, int n8) {
    int i = blockIdx.x * 256 + threadIdx.x;
    if (i >= n8) return;
    float4 a = __ldcs(in + 2 * i), b = __ldcs(in + 2 * i + 1);
    uint4 o;
    o.x = pack2(a.x, a.y); o.y = pack2(a.z, a.w);
    o.z = pack2(b.x, b.y); o.w = pack2(b.z, b.w);
    out[i] = o;
}

// ---------------------------------------------------------------------------
// fp16 gather: warp per row; lane owns CONTIGUOUS elements [lane*8, lane*8+8).
// Pairs are read as uniform broadcast loads (all lanes same address, L1-hit).
__device__ __forceinline__ void gather_row_h(const int* __restrict__ ptr,
                                             const int2* __restrict__ pairs,
                                             const __half* __restrict__ dense,
                                             int row, int lane,
                                             float4& a0, float4& a1) {
    int start = __ldg(ptr + row), end = __ldg(ptr + row + 1);
    #pragma unroll 4
    for (int j = start; j < end; j++) {
        int2 pr = __ldg(pairs + j);                 // uniform across warp
        float v = __int_as_float(pr.y);
        uint4 u = __ldg(reinterpret_cast<const uint4*>(dense + (size_t)pr.x * D) + lane);
        float2 f0 = unpack2(u.x), f1 = unpack2(u.y);
        float2 f2 = unpack2(u.z), f3 = unpack2(u.w);
        a0.x = fmaf(v, f0.x, a0.x); a0.y = fmaf(v, f0.y, a0.y);
        a0.z = fmaf(v, f1.x, a0.z); a0.w = fmaf(v, f1.y, a0.w);
        a1.x = fmaf(v, f2.x, a1.x); a1.y = fmaf(v, f2.y, a1.y);
        a1.z = fmaf(v, f3.x, a1.z); a1.w = fmaf(v, f3.y, a1.w);
    }
}

__global__ void __launch_bounds__(256) spmm_tar_kernel(const int*  __restrict__ ptr,
                                                       const int2* __restrict__ pairs,
                                                       const __half* __restrict__ dense,
                                                       __half* __restrict__ out) {
    int row = (blockIdx.x * 256 + threadIdx.x) >> 5;
    if (row >= N_HE) return;
    int lane = threadIdx.x & 31;
    float4 a0 = make_float4(0.f, 0.f, 0.f, 0.f), a1 = a0;
    gather_row_h(ptr, pairs, dense, row, lane, a0, a1);
    uint4 o;
    o.x = pack2(a0.x, a0.y); o.y = pack2(a0.z, a0.w);
    o.z = pack2(a1.x, a1.y); o.w = pack2(a1.z, a1.w);
    *(reinterpret_cast<uint4*>(out + (size_t)row * D) + lane) = o;   // linear
}

// Fused src-SpMM + epilogue.  a0/a1 are elements [lane*8, lane*8+8).
// LAYER 0: e1 = (relu(msg)*d1 + pois)*d2 ; embs_h = fp16(e1)
// LAYER 1: e2 = (relu(msg)*d1 + e1)*d2 ; out = w0*pois + w1*e1 + w2*e2
template<int LAYER>
__global__ void __launch_bounds__(256) spmm_src_fused_kernel(
    const int*  __restrict__ ptr,
    const int2* __restrict__ pairs,
    const __half* __restrict__ dense,   // msg_tar_h
    const float4* __restrict__ d1,
    const float4* __restrict__ d2,
    const uint4*  __restrict__ prev_h,  // L0: pois_h ; L1: embs_h
    const uint4*  __restrict__ pois_h,  // L1 only
    float4* __restrict__ outp,          // L1: out
    uint4*  __restrict__ out_h)         // L0: embs_h
{
    int row = (blockIdx.x * 256 + threadIdx.x) >> 5;
    if (row >= N_POIS) return;
    int lane = threadIdx.x & 31;
    float4 a0 = make_float4(0.f, 0.f, 0.f, 0.f), a1 = a0;
    gather_row_h(ptr, pairs, dense, row, lane, a0, a1);

    size_t i0 = (size_t)row * (D / 4) + 2 * lane;   // float4 pair for [lane*8, +8)
    size_t ih = (size_t)row * (D / 8) + lane;
    float4 m0 = __ldcs(d1 + i0),  m1 = __ldcs(d1 + i0 + 1);
    float4 q0 = __ldcs(d2 + i0),  q1 = __ldcs(d2 + i0 + 1);

    float4 p0, p1;
    {
        uint4 u = __ldg(prev_h + ih);
        float2 f0 = unpack2(u.x), f1 = unpack2(u.y);
        float2 f2 = unpack2(u.z), f3 = unpack2(u.w);
        p0 = make_float4(f0.x, f0.y, f1.x, f1.y);
        p1 = make_float4(f2.x, f2.y, f3.x, f3.y);
    }

    float4 e0, e1;
    e0.x = (fmaxf(a0.x, 0.f) * m0.x + p0.x) * q0.x;
    e0.y = (fmaxf(a0.y, 0.f) * m0.y + p0.y) * q0.y;
    e0.z = (fmaxf(a0.z, 0.f) * m0.z + p0.z) * q0.z;
    e0.w = (fmaxf(a0.w, 0.f) * m0.w + p0.w) * q0.w;
    e1.x = (fmaxf(a1.x, 0.f) * m1.x + p1.x) * q1.x;
    e1.y = (fmaxf(a1.y, 0.f) * m1.y + p1.y) * q1.y;
    e1.z = (fmaxf(a1.z, 0.f) * m1.z + p1.z) * q1.z;
    e1.w = (fmaxf(a1.w, 0.f) * m1.w + p1.w) * q1.w;

    if (LAYER == 0) {
        uint4 h;
        h.x = pack2(e0.x, e0.y); h.y = pack2(e0.z, e0.w);
        h.z = pack2(e1.x, e1.y); h.w = pack2(e1.z, e1.w);
        out_h[ih] = h;    // linear
    } else {
        float w0 = g_w[0], w1 = g_w[1], w2 = g_w[2];
        float4 z0, z1;
        {
            uint4 u = __ldg(pois_h + ih);
            float2 f0 = unpack2(u.x), f1 = unpack2(u.y);
            float2 f2 = unpack2(u.z), f3 = unpack2(u.w);
            z0 = make_float4(f0.x, f0.y, f1.x, f1.y);
            z1 = make_float4(f2.x, f2.y, f3.x, f3.y);
        }
        float4 o0, o1;
        o0.x = w0 * z0.x + w1 * p0.x + w2 * e0.x;
        o0.y = w0 * z0.y + w1 * p0.y + w2 * e0.y;
        o0.z = w0 * z0.z + w1 * p0.z + w2 * e0.z;
        o0.w = w0 * z0.w + w1 * p0.w + w2 * e0.w;
        o1.x = w0 * z1.x + w1 * p1.x + w2 * e1.x;
        o1.y = w0 * z1.y + w1 * p1.y + w2 * e1.y;
        o1.z = w0 * z1.z + w1 * p1.z + w2 * e1.z;
        o1.w = w0 * z1.w + w1 * p1.w + w2 * e1.w;
        outp[i0]     = o0;
        outp[i0 + 1] = o1;
    }
}

// ---------------------------------------------------------------------------
extern "C" void kernel_launch(void* const* d_in, const int* in_sizes, int n_in,
                              void* d_out, int out_size)
{
    const float* pois      = (const float*)d_in[0];
    const float* tar_vals  = (const float*)d_in[1];
    const float* src_vals  = (const float*)d_in[2];
    const float* attn      = (const float*)d_in[3];
    const float* drop1     = (const float*)d_in[4];
    const float* drop2     = (const float*)d_in[5];
    const int*   tar_rows  = (const int*)d_in[6];
    const int*   tar_cols  = (const int*)d_in[7];
    const int*   src_rows  = (const int*)d_in[8];
    const int*   src_cols  = (const int*)d_in[9];
    float*       out       = (float*)d_out;

    __half *pois_h, *msg_tar_h, *embs_h;
    int *ptr_tar, *cur_tar, *ptr_src, *cur_src, *bsums;
    int2 *pairs_tar, *pairs_src;
    cudaGetSymbolAddress((void**)&pois_h,    g_pois_h);
    cudaGetSymbolAddress((void**)&msg_tar_h, g_msg_tar_h);
    cudaGetSymbolAddress((void**)&embs_h,    g_embs_h);
    cudaGetSymbolAddress((void**)&ptr_tar,   g_ptr_tar);
    cudaGetSymbolAddress((void**)&cur_tar,   g_cur_tar);
    cudaGetSymbolAddress((void**)&pairs_tar, g_pairs_tar);
    cudaGetSymbolAddress((void**)&ptr_src,   g_ptr_src);
    cudaGetSymbolAddress((void**)&cur_src,   g_cur_src);
    cudaGetSymbolAddress((void**)&pairs_src, g_pairs_src);
    cudaGetSymbolAddress((void**)&bsums,     g_bsums);

    // side stream + events, created once on the first (uncaptured) call
    static cudaStream_t s2 = nullptr;
    static cudaEvent_t evF = nullptr, evH = nullptr, evS = nullptr;
    if (s2 == nullptr) {
        cudaStreamCreateWithFlags(&s2, cudaStreamNonBlocking);
        cudaEventCreateWithFlags(&evF, cudaEventDisableTiming);
        cudaEventCreateWithFlags(&evH, cudaEventDisableTiming);
        cudaEventCreateWithFlags(&evS, cudaEventDisableTiming);
    }

    const int nnz8_blocks = (NNZ / 8 + 255) / 256;
    const size_t ld = (size_t)N_POIS * D;
    const int tar_blocks = (N_HE * 32 + 255) / 256;
    const int src_blocks = (N_POIS * 32 + 255) / 256;

    // ---- fork ----
    cudaEventRecord(evF, 0);
    cudaStreamWaitEvent(s2, evF, 0);

    // ---- s2: tohalf, then src CSR build (hidden behind tar path) ----
    tohalf_kernel<<<(N_POIS * D / 8 + 255) / 256, 256, 0, s2>>>(
        (const float4*)pois, (uint4*)pois_h, N_POIS * D / 8);
    cudaEventRecord(evH, s2);
    zero_one_kernel<<<(N_POIS + 1 + 255) / 256, 256, 0, s2>>>(ptr_src, N_POIS + 1, nullptr);
    hist_one_kernel<<<nnz8_blocks, 256, 0, s2>>>((const int4*)src_rows, ptr_src);
    scanA_kernel<<<NB, 256, 0, s2>>>(ptr_src, N_POIS + 1, bsums + NB);
    scanC_kernel<<<NB, 256, 0, s2>>>(ptr_src, N_POIS + 1, bsums + NB, cur_src);
    scatter_one_kernel<<<nnz8_blocks, 256, 0, s2>>>(
        (const int4*)src_rows, (const int4*)src_cols, (const float4*)src_vals,
        cur_src, pairs_src);
    cudaEventRecord(evS, s2);

    // ---- s0: tar CSR build (+softmax) ----
    zero_one_kernel<<<(N_HE + 1 + 255) / 256, 256>>>(ptr_tar, N_HE + 1, attn);
    hist_one_kernel<<<nnz8_blocks, 256>>>((const int4*)tar_rows, ptr_tar);
    scanA_kernel<<<NB, 256>>>(ptr_tar, N_HE + 1, bsums);
    scanC_kernel<<<NB, 256>>>(ptr_tar, N_HE + 1, bsums, cur_tar);
    scatter_one_kernel<<<nnz8_blocks, 256>>>(
        (const int4*)tar_rows, (const int4*)tar_cols, (const float4*)tar_vals,
        cur_tar, pairs_tar);

    // ---- layer 0 ----
    cudaStreamWaitEvent(0, evH, 0);          // need pois_h
    spmm_tar_kernel<<<tar_blocks, 256>>>(ptr_tar, pairs_tar, pois_h, msg_tar_h);
    cudaStreamWaitEvent(0, evS, 0);          // need src CSR (join s2)
    spmm_src_fused_kernel<0><<<src_blocks, 256>>>(ptr_src, pairs_src, msg_tar_h,
        (const float4*)drop1, (const float4*)drop2,
        (const uint4*)pois_h, nullptr, nullptr, (uint4*)embs_h);

    // ---- layer 1 ----
    spmm_tar_kernel<<<tar_blocks, 256>>>(ptr_tar, pairs_tar, embs_h, msg_tar_h);
    spmm_src_fused_kernel<1><<<src_blocks, 256>>>(ptr_src, pairs_src, msg_tar_h,
        (const float4*)(drop1 + ld), (const float4*)(drop2 + ld),
        (const uint4*)embs_h, (const uint4*)pois_h,
        (float4*)out, nullptr);
}

// round 15
// speedup vs baseline: 1.3201x; 1.0112x over previous
#include <cuda_runtime.h>
#include <cuda_fp16.h>

#define N_POIS 100000
#define N_HE   50000
#define NNZ    1600000
#define D      256
#define NB     128          // scan blocks per matrix

// ---------------- scratch (allocation-free device globals) ----------------
__device__ __half g_pois_h[(size_t)N_POIS * D];   // 51.2 MB fp16 gather copy
__device__ __half g_msg_tar_h[(size_t)N_HE * D];  // 25.6 MB fp16 intermediate
__device__ __half g_embs_h[(size_t)N_POIS * D];   // 51.2 MB fp16 e1
__device__ float  g_w[3];

__device__ int  g_cnt_tar[N_HE + 1];    // zero at entry; re-zeroed by scanC
__device__ int  g_cnt_src[N_POIS + 1];
__device__ int  g_ptr_tar[N_HE + 1];
__device__ int  g_cur_tar[N_HE];
__device__ int2 g_pairs_tar[NNZ];
__device__ int  g_ptr_src[N_POIS + 1];
__device__ int  g_cur_src[N_POIS];
__device__ int2 g_pairs_src[NNZ];
__device__ int  g_bsums[2 * NB];

// ---------------------------------------------------------------------------
__device__ __forceinline__ unsigned pack2(float x, float y) {
    __half2 h = __floats2half2_rn(x, y);
    return *reinterpret_cast<unsigned*>(&h);
}
__device__ __forceinline__ float2 unpack2(unsigned u) {
    __half2 h = *reinterpret_cast<__half2*>(&u);
    return __half22float2(h);
}

// ---------------------------------------------------------------------------
// 8 edges per thread, two int4 loads (NNZ % 8 == 0). cnt must be zero at entry.
__global__ void __launch_bounds__(256) hist_one_kernel(const int4* __restrict__ r,
                                                       int* __restrict__ c) {
    int e = blockIdx.x * 256 + threadIdx.x;
    if (e >= NNZ / 8) return;
    int4 a = __ldcs(r + 2 * e);
    int4 b = __ldcs(r + 2 * e + 1);
    atomicAdd(&c[a.x + 1], 1); atomicAdd(&c[a.y + 1], 1);
    atomicAdd(&c[a.z + 1], 1); atomicAdd(&c[a.w + 1], 1);
    atomicAdd(&c[b.x + 1], 1); atomicAdd(&c[b.y + 1], 1);
    atomicAdd(&c[b.z + 1], 1); atomicAdd(&c[b.w + 1], 1);
}

// ---- multi-block scan (single matrix): A (raw block sums) + C (fused) ----
__global__ void __launch_bounds__(256) scanA_kernel(const int* __restrict__ cnt, int len,
                                                    int* __restrict__ bsums) {
    __shared__ int red[256];
    int chunk = (len + NB - 1) / NB;
    int lo = blockIdx.x * chunk, hi = min(len, lo + chunk);
    int sub = (chunk + 255) >> 8;
    int a = lo + threadIdx.x * sub, b = min(hi, a + sub);
    int s = 0;
    for (int i = a; i < b; i++) s += cnt[i];
    red[threadIdx.x] = s;
    __syncthreads();
    for (int d = 128; d > 0; d >>= 1) {
        if (threadIdx.x < d) red[threadIdx.x] += red[threadIdx.x + d];
        __syncthreads();
    }
    if (threadIdx.x == 0) bsums[blockIdx.x] = red[0];
}

// scanC: reads cnt, writes ptr + cur, and RE-ZEROS cnt (restores the
// zero-at-entry invariant for the next replay). In-kernel parallel scan of
// the NB raw block sums — no extra launch, NO cross-block synchronization.
__global__ void __launch_bounds__(256) scanC_kernel(int* __restrict__ cnt, int len,
                                                    const int* __restrict__ bsums,
                                                    int* __restrict__ ptr,
                                                    int* __restrict__ cur) {
    __shared__ int s[256];
    __shared__ int bs[NB];
    int t = threadIdx.x;
    int blk = blockIdx.x;

    // inclusive scan of the NB raw block sums (log steps, parallel)
    if (t < NB) bs[t] = bsums[t];
    __syncthreads();
    for (int d = 1; d < NB; d <<= 1) {
        int v = (t >= d && t < NB) ? bs[t - d] : 0;
        __syncthreads();
        if (t < NB) bs[t] += v;
        __syncthreads();
    }
    int base = (blk == 0) ? 0 : bs[blk - 1];

    int chunk = (len + NB - 1) / NB;
    int lo = blk * chunk, hi = min(len, lo + chunk);
    int sub = (chunk + 255) >> 8;
    int a = lo + t * sub, b = min(hi, a + sub);
    int sum = 0;
    for (int i = a; i < b; i++) sum += cnt[i];
    s[t] = sum;
    __syncthreads();
    int acc = s[t];
    for (int d = 1; d < 256; d <<= 1) {
        int v = (t >= d) ? s[t - d] : 0;
        __syncthreads();
        s[t] = acc = acc + v;
        __syncthreads();
        acc = s[t];
    }
    int off = base + ((t == 0) ? 0 : s[t - 1]);
    for (int i = a; i < b; i++) {
        off += cnt[i];
        ptr[i] = off;
        if (i < len - 1) cur[i] = off;    // cur[row] = ptr[row]
        cnt[i] = 0;                       // restore zero invariant
    }
}

// 8 edges per thread, two int4/float4 loads each
__global__ void __launch_bounds__(256) scatter_one_kernel(
    const int4* __restrict__ r4, const int4* __restrict__ c4,
    const float4* __restrict__ v4, int* __restrict__ cur, int2* __restrict__ pairs)
{
    int e = blockIdx.x * 256 + threadIdx.x;
    if (e >= NNZ / 8) return;
    int4   r0 = __ldcs(r4 + 2 * e),     r1 = __ldcs(r4 + 2 * e + 1);
    int4   c0 = __ldcs(c4 + 2 * e),     c1 = __ldcs(c4 + 2 * e + 1);
    float4 v0 = __ldcs(v4 + 2 * e),     v1 = __ldcs(v4 + 2 * e + 1);
    pairs[atomicAdd(&cur[r0.x], 1)] = make_int2(c0.x, __float_as_int(v0.x));
    pairs[atomicAdd(&cur[r0.y], 1)] = make_int2(c0.y, __float_as_int(v0.y));
    pairs[atomicAdd(&cur[r0.z], 1)] = make_int2(c0.z, __float_as_int(v0.z));
    pairs[atomicAdd(&cur[r0.w], 1)] = make_int2(c0.w, __float_as_int(v0.w));
    pairs[atomicAdd(&cur[r1.x], 1)] = make_int2(c1.x, __float_as_int(v1.x));
    pairs[atomicAdd(&cur[r1.y], 1)] = make_int2(c1.y, __float_as_int(v1.y));
    pairs[atomicAdd(&cur[r1.z], 1)] = make_int2(c1.z, __float_as_int(v1.z));
    pairs[atomicAdd(&cur[r1.w], 1)] = make_int2(c1.w, __float_as_int(v1.w));
}

// fp32 -> fp16 copy (8 elems/thread), LINEAR layout; thread 0 also does softmax
__global__ void __launch_bounds__(256) tohalf_kernel(const float4* __restrict__ in,
                                                     uint4* __restrict__ out, int n8,
                                                     const float* __restrict__ attn) {
    int i = blockIdx.x * 256 + threadIdx.x;
    if (i == 0) {
        float a0 = attn[0], a1 = attn[1], a2 = attn[2];
        float m = fmaxf(a0, fmaxf(a1, a2));
        float e0 = expf(a0 - m), e1 = expf(a1 - m), e2 = expf(a2 - m);
        float inv = 1.0f / (e0 + e1 + e2);
        g_w[0] = e0 * inv; g_w[1] = e1 * inv; g_w[2] = e2 * inv;
    }
    if (i >= n8) return;
    float4 a = __ldcs(in + 2 * i), b = __ldcs(in + 2 * i + 1);
    uint4 o;
    o.x = pack2(a.x, a.y); o.y = pack2(a.z, a.w);
    o.z = pack2(b.x, b.y); o.w = pack2(b.z, b.w);
    out[i] = o;
}

// ---------------------------------------------------------------------------
// fp16 gather: warp per row; lane owns CONTIGUOUS elements [lane*8, lane*8+8).
// Pairs are read as uniform broadcast loads (all lanes same address, L1-hit).
__device__ __forceinline__ void gather_row_h(const int* __restrict__ ptr,
                                             const int2* __restrict__ pairs,
                                             const __half* __restrict__ dense,
                                             int row, int lane,
                                             float4& a0, float4& a1) {
    int start = __ldg(ptr + row), end = __ldg(ptr + row + 1);
    #pragma unroll 4
    for (int j = start; j < end; j++) {
        int2 pr = __ldg(pairs + j);                 // uniform across warp
        float v = __int_as_float(pr.y);
        uint4 u = __ldg(reinterpret_cast<const uint4*>(dense + (size_t)pr.x * D) + lane);
        float2 f0 = unpack2(u.x), f1 = unpack2(u.y);
        float2 f2 = unpack2(u.z), f3 = unpack2(u.w);
        a0.x = fmaf(v, f0.x, a0.x); a0.y = fmaf(v, f0.y, a0.y);
        a0.z = fmaf(v, f1.x, a0.z); a0.w = fmaf(v, f1.y, a0.w);
        a1.x = fmaf(v, f2.x, a1.x); a1.y = fmaf(v, f2.y, a1.y);
        a1.z = fmaf(v, f3.x, a1.z); a1.w = fmaf(v, f3.y, a1.w);
    }
}

__global__ void __launch_bounds__(256) spmm_tar_kernel(const int*  __restrict__ ptr,
                                                       const int2* __restrict__ pairs,
                                                       const __half* __restrict__ dense,
                                                       __half* __restrict__ out) {
    int row = (blockIdx.x * 256 + threadIdx.x) >> 5;
    if (row >= N_HE) return;
    int lane = threadIdx.x & 31;
    float4 a0 = make_float4(0.f, 0.f, 0.f, 0.f), a1 = a0;
    gather_row_h(ptr, pairs, dense, row, lane, a0, a1);
    uint4 o;
    o.x = pack2(a0.x, a0.y); o.y = pack2(a0.z, a0.w);
    o.z = pack2(a1.x, a1.y); o.w = pack2(a1.z, a1.w);
    *(reinterpret_cast<uint4*>(out + (size_t)row * D) + lane) = o;   // linear
}

// Fused src-SpMM + epilogue.  a0/a1 are elements [lane*8, lane*8+8).
// LAYER 0: e1 = (relu(msg)*d1 + pois)*d2 ; embs_h = fp16(e1)
// LAYER 1: e2 = (relu(msg)*d1 + e1)*d2 ; out = w0*pois + w1*e1 + w2*e2
template<int LAYER>
__global__ void __launch_bounds__(256) spmm_src_fused_kernel(
    const int*  __restrict__ ptr,
    const int2* __restrict__ pairs,
    const __half* __restrict__ dense,   // msg_tar_h
    const float4* __restrict__ d1,
    const float4* __restrict__ d2,
    const uint4*  __restrict__ prev_h,  // L0: pois_h ; L1: embs_h
    const uint4*  __restrict__ pois_h,  // L1 only
    float4* __restrict__ outp,          // L1: out
    uint4*  __restrict__ out_h)         // L0: embs_h
{
    int row = (blockIdx.x * 256 + threadIdx.x) >> 5;
    if (row >= N_POIS) return;
    int lane = threadIdx.x & 31;
    float4 a0 = make_float4(0.f, 0.f, 0.f, 0.f), a1 = a0;
    gather_row_h(ptr, pairs, dense, row, lane, a0, a1);

    size_t i0 = (size_t)row * (D / 4) + 2 * lane;   // float4 pair for [lane*8, +8)
    size_t ih = (size_t)row * (D / 8) + lane;
    float4 m0 = __ldcs(d1 + i0),  m1 = __ldcs(d1 + i0 + 1);
    float4 q0 = __ldcs(d2 + i0),  q1 = __ldcs(d2 + i0 + 1);

    float4 p0, p1;
    {
        uint4 u = __ldg(prev_h + ih);
        float2 f0 = unpack2(u.x), f1 = unpack2(u.y);
        float2 f2 = unpack2(u.z), f3 = unpack2(u.w);
        p0 = make_float4(f0.x, f0.y, f1.x, f1.y);
        p1 = make_float4(f2.x, f2.y, f3.x, f3.y);
    }

    float4 e0, e1;
    e0.x = (fmaxf(a0.x, 0.f) * m0.x + p0.x) * q0.x;
    e0.y = (fmaxf(a0.y, 0.f) * m0.y + p0.y) * q0.y;
    e0.z = (fmaxf(a0.z, 0.f) * m0.z + p0.z) * q0.z;
    e0.w = (fmaxf(a0.w, 0.f) * m0.w + p0.w) * q0.w;
    e1.x = (fmaxf(a1.x, 0.f) * m1.x + p1.x) * q1.x;
    e1.y = (fmaxf(a1.y, 0.f) * m1.y + p1.y) * q1.y;
    e1.z = (fmaxf(a1.z, 0.f) * m1.z + p1.z) * q1.z;
    e1.w = (fmaxf(a1.w, 0.f) * m1.w + p1.w) * q1.w;

    if (LAYER == 0) {
        uint4 h;
        h.x = pack2(e0.x, e0.y); h.y = pack2(e0.z, e0.w);
        h.z = pack2(e1.x, e1.y); h.w = pack2(e1.z, e1.w);
        out_h[ih] = h;    // linear
    } else {
        float w0 = g_w[0], w1 = g_w[1], w2 = g_w[2];
        float4 z0, z1;
        {
            uint4 u = __ldg(pois_h + ih);
            float2 f0 = unpack2(u.x), f1 = unpack2(u.y);
            float2 f2 = unpack2(u.z), f3 = unpack2(u.w);
            z0 = make_float4(f0.x, f0.y, f1.x, f1.y);
            z1 = make_float4(f2.x, f2.y, f3.x, f3.y);
        }
        float4 o0, o1;
        o0.x = w0 * z0.x + w1 * p0.x + w2 * e0.x;
        o0.y = w0 * z0.y + w1 * p0.y + w2 * e0.y;
        o0.z = w0 * z0.z + w1 * p0.z + w2 * e0.z;
        o0.w = w0 * z0.w + w1 * p0.w + w2 * e0.w;
        o1.x = w0 * z1.x + w1 * p1.x + w2 * e1.x;
        o1.y = w0 * z1.y + w1 * p1.y + w2 * e1.y;
        o1.z = w0 * z1.z + w1 * p1.z + w2 * e1.z;
        o1.w = w0 * z1.w + w1 * p1.w + w2 * e1.w;
        outp[i0]     = o0;
        outp[i0 + 1] = o1;
    }
}

// ---------------------------------------------------------------------------
extern "C" void kernel_launch(void* const* d_in, const int* in_sizes, int n_in,
                              void* d_out, int out_size)
{
    const float* pois      = (const float*)d_in[0];
    const float* tar_vals  = (const float*)d_in[1];
    const float* src_vals  = (const float*)d_in[2];
    const float* attn      = (const float*)d_in[3];
    const float* drop1     = (const float*)d_in[4];
    const float* drop2     = (const float*)d_in[5];
    const int*   tar_rows  = (const int*)d_in[6];
    const int*   tar_cols  = (const int*)d_in[7];
    const int*   src_rows  = (const int*)d_in[8];
    const int*   src_cols  = (const int*)d_in[9];
    float*       out       = (float*)d_out;

    __half *pois_h, *msg_tar_h, *embs_h;
    int *cnt_tar, *cnt_src, *ptr_tar, *cur_tar, *ptr_src, *cur_src, *bsums;
    int2 *pairs_tar, *pairs_src;
    cudaGetSymbolAddress((void**)&pois_h,    g_pois_h);
    cudaGetSymbolAddress((void**)&msg_tar_h, g_msg_tar_h);
    cudaGetSymbolAddress((void**)&embs_h,    g_embs_h);
    cudaGetSymbolAddress((void**)&cnt_tar,   g_cnt_tar);
    cudaGetSymbolAddress((void**)&cnt_src,   g_cnt_src);
    cudaGetSymbolAddress((void**)&ptr_tar,   g_ptr_tar);
    cudaGetSymbolAddress((void**)&cur_tar,   g_cur_tar);
    cudaGetSymbolAddress((void**)&pairs_tar, g_pairs_tar);
    cudaGetSymbolAddress((void**)&ptr_src,   g_ptr_src);
    cudaGetSymbolAddress((void**)&cur_src,   g_cur_src);
    cudaGetSymbolAddress((void**)&pairs_src, g_pairs_src);
    cudaGetSymbolAddress((void**)&bsums,     g_bsums);

    // side stream + events, created once on the first (uncaptured) call
    static cudaStream_t s2 = nullptr;
    static cudaEvent_t evF = nullptr, evH = nullptr, evS = nullptr;
    if (s2 == nullptr) {
        cudaStreamCreateWithFlags(&s2, cudaStreamNonBlocking);
        cudaEventCreateWithFlags(&evF, cudaEventDisableTiming);
        cudaEventCreateWithFlags(&evH, cudaEventDisableTiming);
        cudaEventCreateWithFlags(&evS, cudaEventDisableTiming);
    }

    const int nnz8_blocks = (NNZ / 8 + 255) / 256;
    const size_t ld = (size_t)N_POIS * D;
    const int tar_blocks = (N_HE * 32 + 255) / 256;
    const int src_blocks = (N_POIS * 32 + 255) / 256;

    // ---- fork ----
    cudaEventRecord(evF, 0);
    cudaStreamWaitEvent(s2, evF, 0);

    // ---- s2: tohalf(+softmax), then src CSR build (hidden behind tar path) ----
    tohalf_kernel<<<(N_POIS * D / 8 + 255) / 256, 256, 0, s2>>>(
        (const float4*)pois, (uint4*)pois_h, N_POIS * D / 8, attn);
    cudaEventRecord(evH, s2);
    hist_one_kernel<<<nnz8_blocks, 256, 0, s2>>>((const int4*)src_rows, cnt_src);
    scanA_kernel<<<NB, 256, 0, s2>>>(cnt_src, N_POIS + 1, bsums + NB);
    scanC_kernel<<<NB, 256, 0, s2>>>(cnt_src, N_POIS + 1, bsums + NB, ptr_src, cur_src);
    scatter_one_kernel<<<nnz8_blocks, 256, 0, s2>>>(
        (const int4*)src_rows, (const int4*)src_cols, (const float4*)src_vals,
        cur_src, pairs_src);
    cudaEventRecord(evS, s2);

    // ---- s0: tar CSR build (no zero kernel — cnt self-restoring) ----
    hist_one_kernel<<<nnz8_blocks, 256>>>((const int4*)tar_rows, cnt_tar);
    scanA_kernel<<<NB, 256>>>(cnt_tar, N_HE + 1, bsums);
    scanC_kernel<<<NB, 256>>>(cnt_tar, N_HE + 1, bsums, ptr_tar, cur_tar);
    scatter_one_kernel<<<nnz8_blocks, 256>>>(
        (const int4*)tar_rows, (const int4*)tar_cols, (const float4*)tar_vals,
        cur_tar, pairs_tar);

    // ---- layer 0 ----
    cudaStreamWaitEvent(0, evH, 0);          // need pois_h
    spmm_tar_kernel<<<tar_blocks, 256>>>(ptr_tar, pairs_tar, pois_h, msg_tar_h);
    cudaStreamWaitEvent(0, evS, 0);          // need src CSR (join s2)
    spmm_src_fused_kernel<0><<<src_blocks, 256>>>(ptr_src, pairs_src, msg_tar_h,
        (const float4*)drop1, (const float4*)drop2,
        (const uint4*)pois_h, nullptr, nullptr, (uint4*)embs_h);

    // ---- layer 1 ----
    spmm_tar_kernel<<<tar_blocks, 256>>>(ptr_tar, pairs_tar, embs_h, msg_tar_h);
    spmm_src_fused_kernel<1><<<src_blocks, 256>>>(ptr_src, pairs_src, msg_tar_h,
        (const float4*)(drop1 + ld), (const float4*)(drop2 + ld),
        (const uint4*)embs_h, (const uint4*)pois_h,
        (float4*)out, nullptr);
}